// round 4
// baseline (speedup 1.0000x reference)
#include <cuda_runtime.h>
#include <cuda_bf16.h>
#include <math.h>
#include <stdint.h>
#include <stddef.h>

// ---------------------------------------------------------------------------
// bwd_mpgnn: 6-level MPGNN. Every layer is  C = tanh((A [+ R]) @ W^T + bias).
//
// GEMM core: emulated-fp32 via 3x bf16 mma.sync.m16n8k16 (split each fp32
// operand into bf16 hi + bf16 lo residual; compute hi*hi + hi*lo + lo*hi,
// accumulate fp32).  Error per product ~2^-16 -> passes 1e-3 easily.
//
// Tile: BM=128 x BN=128 x BK=16, 8 warps (4x2), warp tile 32x64,
// per-warp 2x8 m16n8k16 fragments x 3 MMAs. Double-buffered smem,
// register-prefetched global loads.
// ---------------------------------------------------------------------------

#define NN 32768           // nodes per level
#define BM 128
#define BN 128
#define BK 16
#define SROW 17            // smem row stride in uint32 (16 pairs + 1 pad)

// Scratch (device globals: allocation-free rule)
__device__ float g_X1[(size_t)NN * 512];   // [e, 0] concat input
__device__ float g_X2[(size_t)NN * 512];   // [e1, r] concat input
__device__ float g_H1[(size_t)NN * 512];
__device__ float g_H2[(size_t)NN * 512];
__device__ float g_T0[(size_t)NN * 256];
__device__ float g_T1[(size_t)NN * 256];
__device__ float g_T2[(size_t)NN * 256];
__device__ float g_MS[(size_t)NN * 256];

// split two consecutive fp32 into packed bf16x2 (hi) and bf16x2 (lo residual)
__device__ __forceinline__ void split2(float x, float y,
                                       unsigned& hi, unsigned& lo)
{
    __nv_bfloat16 hx = __float2bfloat16_rn(x);
    __nv_bfloat16 hy = __float2bfloat16_rn(y);
    __nv_bfloat16 lx = __float2bfloat16_rn(x - __bfloat162float(hx));
    __nv_bfloat16 ly = __float2bfloat16_rn(y - __bfloat162float(hy));
    unsigned uhx = __bfloat16_as_ushort(hx), uhy = __bfloat16_as_ushort(hy);
    unsigned ulx = __bfloat16_as_ushort(lx), uly = __bfloat16_as_ushort(ly);
    hi = uhx | (uhy << 16);
    lo = ulx | (uly << 16);
}

__device__ __forceinline__ void mma_bf16(float* c, const unsigned* a,
                                         const unsigned* b)
{
    asm volatile(
        "mma.sync.aligned.m16n8k16.row.col.f32.bf16.bf16.f32 "
        "{%0,%1,%2,%3}, {%4,%5,%6,%7}, {%8,%9}, {%0,%1,%2,%3};"
        : "+f"(c[0]), "+f"(c[1]), "+f"(c[2]), "+f"(c[3])
        : "r"(a[0]), "r"(a[1]), "r"(a[2]), "r"(a[3]),
          "r"(b[0]), "r"(b[1]));
}

__global__ __launch_bounds__(256)
void gemm_tanh_ef32(const float* __restrict__ A, int lda,
                    const float* __restrict__ Rr, int ldr,
                    const float* __restrict__ W,        // [Nout, K]
                    const float* __restrict__ bias,     // [Nout]
                    float* __restrict__ C, int ldc,
                    int K)
{
    // layout: [buf][row][pair]; pairs 0..7 = hi (k=2p, 2p+1), 8..15 = lo
    __shared__ unsigned As[2][BM][SROW];
    __shared__ unsigned Ws[2][BN][SROW];

    const int tid  = threadIdx.x;
    const int lane = tid & 31;
    const int warp = tid >> 5;
    const int wm   = warp >> 1;     // 0..3  (32 rows each)
    const int wn   = warp & 1;      // 0..1  (64 cols each)
    const int l4   = lane & 3;
    const int lg   = lane >> 2;
    const int row0 = blockIdx.y * BM;
    const int col0 = blockIdx.x * BN;

    float acc[2][8][4];
    #pragma unroll
    for (int i = 0; i < 2; i++)
        #pragma unroll
        for (int j = 0; j < 8; j++)
            #pragma unroll
            for (int k = 0; k < 4; k++) acc[i][j][k] = 0.f;

    // Loader: tile is 128 rows x 16 k-floats = 512 float4; 2 per thread.
    const int akq  = (tid & 3) * 4;   // k offset within tile (0,4,8,12)
    const int kp   = akq >> 1;        // pair index base (0,2,4,6)
    const int arow = tid >> 2;        // row 0..63 (+64 on pass 2)

    float4 pa[2], pw[2];
    const int nk = K / BK;

    // prefetch tile 0
    #pragma unroll
    for (int i = 0; i < 2; i++) {
        int r = arow + i * 64;
        pa[i] = *(const float4*)(A + (size_t)(row0 + r) * lda + akq);
        if (Rr) {
            float4 t = *(const float4*)(Rr + (size_t)(row0 + r) * ldr + akq);
            pa[i].x += t.x; pa[i].y += t.y; pa[i].z += t.z; pa[i].w += t.w;
        }
        pw[i] = *(const float4*)(W + (size_t)(col0 + r) * K + akq);
    }

    for (int it = 0; it < nk; it++) {
        const int b = it & 1;

        // split fp32 -> bf16 hi/lo, store packed pairs
        #pragma unroll
        for (int i = 0; i < 2; i++) {
            int r = arow + i * 64;
            unsigned h0, l0, h1, l1;
            split2(pa[i].x, pa[i].y, h0, l0);
            split2(pa[i].z, pa[i].w, h1, l1);
            As[b][r][kp    ] = h0;  As[b][r][kp + 1] = h1;
            As[b][r][kp + 8] = l0;  As[b][r][kp + 9] = l1;
            split2(pw[i].x, pw[i].y, h0, l0);
            split2(pw[i].z, pw[i].w, h1, l1);
            Ws[b][r][kp    ] = h0;  Ws[b][r][kp + 1] = h1;
            Ws[b][r][kp + 8] = l0;  Ws[b][r][kp + 9] = l1;
        }
        __syncthreads();

        // prefetch next tile (overlaps MMA below)
        if (it + 1 < nk) {
            int kt = (it + 1) * BK;
            #pragma unroll
            for (int i = 0; i < 2; i++) {
                int r = arow + i * 64;
                pa[i] = *(const float4*)(A + (size_t)(row0 + r) * lda + kt + akq);
                if (Rr) {
                    float4 t = *(const float4*)(Rr + (size_t)(row0 + r) * ldr + kt + akq);
                    pa[i].x += t.x; pa[i].y += t.y; pa[i].z += t.z; pa[i].w += t.w;
                }
                pw[i] = *(const float4*)(W + (size_t)(col0 + r) * K + kt + akq);
            }
        }

        // fragments: m16n8k16  A: a0=(r, 2l4..), a1=(r+8,..), a2=(r, 8+2l4..), a3=(r+8, 8+..)
        unsigned ah[2][4], al[2][4];
        #pragma unroll
        for (int mt = 0; mt < 2; mt++) {
            int mb = wm * 32 + mt * 16;
            ah[mt][0] = As[b][mb + lg    ][l4    ];
            ah[mt][1] = As[b][mb + lg + 8][l4    ];
            ah[mt][2] = As[b][mb + lg    ][l4 + 4];
            ah[mt][3] = As[b][mb + lg + 8][l4 + 4];
            al[mt][0] = As[b][mb + lg    ][l4 + 8];
            al[mt][1] = As[b][mb + lg + 8][l4 + 8];
            al[mt][2] = As[b][mb + lg    ][l4 + 12];
            al[mt][3] = As[b][mb + lg + 8][l4 + 12];
        }
        #pragma unroll
        for (int nt = 0; nt < 8; nt++) {
            int nb = wn * 64 + nt * 8;
            unsigned bh[2], bl[2];
            bh[0] = Ws[b][nb + lg][l4    ];
            bh[1] = Ws[b][nb + lg][l4 + 4];
            bl[0] = Ws[b][nb + lg][l4 + 8];
            bl[1] = Ws[b][nb + lg][l4 + 12];
            #pragma unroll
            for (int mt = 0; mt < 2; mt++) {
                mma_bf16(acc[mt][nt], ah[mt], bh);   // hi*hi
                mma_bf16(acc[mt][nt], al[mt], bh);   // lo*hi
                mma_bf16(acc[mt][nt], ah[mt], bl);   // hi*lo
            }
        }
        // single barrier per iteration is sufficient: a warp storing buffer b
        // at iteration it+2 has passed the barrier at it+1, which every warp
        // reaches only after finishing compute of iteration it.
    }

    // epilogue: bias + tanh, float2 stores
    #pragma unroll
    for (int mt = 0; mt < 2; mt++) {
        int r = row0 + wm * 32 + mt * 16 + lg;
        #pragma unroll
        for (int nt = 0; nt < 8; nt++) {
            int c  = col0 + wn * 64 + nt * 8 + 2 * l4;
            float b0 = bias[c], b1 = bias[c + 1];
            float2 v;
            v.x = tanhf(acc[mt][nt][0] + b0);
            v.y = tanhf(acc[mt][nt][1] + b1);
            *(float2*)(C + (size_t)r * ldc + c) = v;
            v.x = tanhf(acc[mt][nt][2] + b0);
            v.y = tanhf(acc[mt][nt][3] + b1);
            *(float2*)(C + (size_t)(r + 8) * ldc + c) = v;
        }
    }
}

// msgs[n,:] = sum_{k<8} prev[idx[n,k], :]   (256 floats/row)
__global__ __launch_bounds__(256)
void gather_sum(const float* __restrict__ prev, const int* __restrict__ idx,
                float* __restrict__ outp)
{
    int n  = blockIdx.x * 4 + (threadIdx.x >> 6);
    int c4 = (threadIdx.x & 63) * 4;
    const int* ip = idx + (size_t)n * 8;
    float4 s = make_float4(0.f, 0.f, 0.f, 0.f);
    #pragma unroll
    for (int k = 0; k < 8; k++) {
        int j = __ldg(ip + k);
        float4 v = *(const float4*)(prev + (size_t)j * 256 + c4);
        s.x += v.x; s.y += v.y; s.z += v.z; s.w += v.w;
    }
    *(float4*)(outp + (size_t)n * 256 + c4) = s;
}

// zero upper half of X1 (the "concat with zeros" branch)
__global__ void zero_upper_k(float* X1)
{
    X1[(size_t)blockIdx.x * 512 + 256 + threadIdx.x] = 0.f;
}

// ---------------------------------------------------------------------------

extern "C" void kernel_launch(void* const* d_in, const int* in_sizes, int n_in,
                              void* d_out, int out_size)
{
    const float* feats = (const float*)d_in[0];   // [6, NN, 32]
    const int*   pred  = (const int*)  d_in[1];   // [5, NN, 8]
    const float* We    = (const float*)d_in[2];   // [256, 32]
    const float* be    = (const float*)d_in[3];   // [256]
    const float* rsW1  = (const float*)d_in[4];   // [12,256,256]
    const float* rsb1  = (const float*)d_in[5];
    const float* rsW2  = (const float*)d_in[6];
    const float* rsb2  = (const float*)d_in[7];
    const float* rsW3  = (const float*)d_in[8];
    const float* rsb3  = (const float*)d_in[9];
    const float* rcW1  = (const float*)d_in[10];  // [6,512,512]
    const float* rcb1  = (const float*)d_in[11];
    const float* rcW2  = (const float*)d_in[12];
    const float* rcb2  = (const float*)d_in[13];
    const float* rcW3  = (const float*)d_in[14];  // [6,256,512]
    const float* rcb3  = (const float*)d_in[15];
    float* out = (float*)d_out;                   // [6, NN, 256]

    float *X1, *X2, *H1, *H2, *T0, *T1, *T2, *MS;
    cudaGetSymbolAddress((void**)&X1, g_X1);
    cudaGetSymbolAddress((void**)&X2, g_X2);
    cudaGetSymbolAddress((void**)&H1, g_H1);
    cudaGetSymbolAddress((void**)&H2, g_H2);
    cudaGetSymbolAddress((void**)&T0, g_T0);
    cudaGetSymbolAddress((void**)&T1, g_T1);
    cudaGetSymbolAddress((void**)&T2, g_T2);
    cudaGetSymbolAddress((void**)&MS, g_MS);

    auto G = [&](const float* A, int lda, const float* R, int ldr,
                 const float* W, const float* b, float* C, int ldc,
                 int Nout, int K) {
        dim3 grid(Nout / BN, NN / BM);
        gemm_tanh_ef32<<<grid, 256>>>(A, lda, R, ldr, W, b, C, ldc, K);
    };

    // X1 upper 256 cols = zeros (concat(e, zeros)); stays zero all levels
    zero_upper_k<<<NN, 256>>>(X1);

    // level 0: out[0] = tanh(feats[0] @ We^T + be)
    G(feats, 32, nullptr, 0, We, be, out, 256, 256, 32);

    for (int l = 1; l < 6; l++) {
        int d = l - 1; if (d > 2) d = 2;
        const float* fl   = feats + (size_t)l * NN * 32;
        float*       OUT  = out   + (size_t)l * NN * 256;
        const float* PREV = out   + (size_t)(l - 1) * NN * 256;

        // embed -> X1[:, 0:256]
        G(fl, 32, nullptr, 0, We, be, X1, 512, 256, 32);

        // big resnet (3+d) on X1=[e,0]
        int bc = 3 + d;
        G(X1, 512, nullptr, 0, rcW1 + (size_t)bc * 512 * 512, rcb1 + bc * 512, H1, 512, 512, 512);
        G(H1, 512, nullptr, 0, rcW2 + (size_t)bc * 512 * 512, rcb2 + bc * 512, H2, 512, 512, 512);
        G(H2, 512, X1, 512,   rcW3 + (size_t)bc * 256 * 512, rcb3 + bc * 256, T0, 256, 256, 512);

        // small resnet (9+d) on z=T0 -> e1 into X2[:, 0:256]
        int s = 9 + d;
        G(T0, 256, nullptr, 0, rsW1 + (size_t)s * 65536, rsb1 + s * 256, T1, 256, 256, 256);
        G(T1, 256, nullptr, 0, rsW2 + (size_t)s * 65536, rsb2 + s * 256, T2, 256, 256, 256);
        G(T2, 256, T0, 256,    rsW3 + (size_t)s * 65536, rsb3 + s * 256, X2, 512, 256, 256);

        // messages: gather-sum predecessors from previous level
        gather_sum<<<NN / 4, 256>>>(PREV, pred + (size_t)(l - 1) * NN * 8, MS);

        // small resnet (2d) on msgs
        s = 2 * d;
        G(MS, 256, nullptr, 0, rsW1 + (size_t)s * 65536, rsb1 + s * 256, T0, 256, 256, 256);
        G(T0, 256, nullptr, 0, rsW2 + (size_t)s * 65536, rsb2 + s * 256, T1, 256, 256, 256);
        G(T1, 256, MS, 256,    rsW3 + (size_t)s * 65536, rsb3 + s * 256, T2, 256, 256, 256);

        // small resnet (2d+1) on r=T2 -> r into X2[:, 256:512]
        s = 2 * d + 1;
        G(T2, 256, nullptr, 0, rsW1 + (size_t)s * 65536, rsb1 + s * 256, T0, 256, 256, 256);
        G(T0, 256, nullptr, 0, rsW2 + (size_t)s * 65536, rsb2 + s * 256, T1, 256, 256, 256);
        G(T1, 256, T2, 256,    rsW3 + (size_t)s * 65536, rsb3 + s * 256, X2 + 256, 512, 256, 256);

        // big resnet (d) on X2=[e1, r]
        G(X2, 512, nullptr, 0, rcW1 + (size_t)d * 512 * 512, rcb1 + d * 512, H1, 512, 512, 512);
        G(H1, 512, nullptr, 0, rcW2 + (size_t)d * 512 * 512, rcb2 + d * 512, H2, 512, 512, 512);
        G(H2, 512, X2, 512,   rcW3 + (size_t)d * 256 * 512, rcb3 + d * 256, T0, 256, 256, 512);

        // small resnet (6+d) -> out[l]
        s = 6 + d;
        G(T0, 256, nullptr, 0, rsW1 + (size_t)s * 65536, rsb1 + s * 256, T1, 256, 256, 256);
        G(T1, 256, nullptr, 0, rsW2 + (size_t)s * 65536, rsb2 + s * 256, T2, 256, 256, 256);
        G(T2, 256, T0, 256,    rsW3 + (size_t)s * 65536, rsb3 + s * 256, OUT, 256, 256, 256);
    }
}

// round 6
// speedup vs baseline: 1.3044x; 1.3044x over previous
#include <cuda_runtime.h>
#include <cuda_bf16.h>
#include <math.h>
#include <stdint.h>
#include <stddef.h>

// ---------------------------------------------------------------------------
// bwd_mpgnn: 6-level MPGNN. Every layer: C = tanh((A [+ R]) @ W^T + bias).
//
// GEMM core: emulated-fp32 via 3x bf16 mma.sync.m16n8k16 (hi/lo split:
// hi*hi + lo*hi + hi*lo, fp32 accumulate).  Fragments loaded with
// ldmatrix.x4 (12 LDSM vs 48 scalar LDS per warp per k-tile), smem row
// stride 20 words -> conflict-free LDSM phases.
// Tile: BM=128 x BN=128 x BK=16, 8 warps (4x2), warp tile 32x64.
// ---------------------------------------------------------------------------

#define NN 32768
#define BM 128
#define BN 128
#define BK 16
#define SROW 20            // smem row stride in words (16 data + 4 pad)

// Scratch (device globals: allocation-free rule)
__device__ float g_X1[(size_t)NN * 512];   // [e, 0] concat input
__device__ float g_X2[(size_t)NN * 512];   // [e1, r] concat input
__device__ float g_H1[(size_t)NN * 512];
__device__ float g_H2[(size_t)NN * 512];
__device__ float g_T0[(size_t)NN * 256];
__device__ float g_T1[(size_t)NN * 256];
__device__ float g_T2[(size_t)NN * 256];
__device__ float g_MS[(size_t)NN * 256];

__device__ __forceinline__ uint32_t smem_u32(const void* p) {
    uint32_t a;
    asm("{ .reg .u64 t; cvta.to.shared.u64 t, %1; cvt.u32.u64 %0, t; }"
        : "=r"(a) : "l"(p));
    return a;
}

// split two consecutive fp32 into packed bf16x2 (hi) and bf16x2 (lo residual)
__device__ __forceinline__ void split2(float x, float y,
                                       unsigned& hi, unsigned& lo)
{
    __nv_bfloat16 hx = __float2bfloat16_rn(x);
    __nv_bfloat16 hy = __float2bfloat16_rn(y);
    __nv_bfloat16 lx = __float2bfloat16_rn(x - __bfloat162float(hx));
    __nv_bfloat16 ly = __float2bfloat16_rn(y - __bfloat162float(hy));
    hi = (unsigned)__bfloat16_as_ushort(hx) | ((unsigned)__bfloat16_as_ushort(hy) << 16);
    lo = (unsigned)__bfloat16_as_ushort(lx) | ((unsigned)__bfloat16_as_ushort(ly) << 16);
}

__device__ __forceinline__ void mma_bf16(float* c, const unsigned* a,
                                         const unsigned* b)
{
    asm volatile(
        "mma.sync.aligned.m16n8k16.row.col.f32.bf16.bf16.f32 "
        "{%0,%1,%2,%3}, {%4,%5,%6,%7}, {%8,%9}, {%0,%1,%2,%3};"
        : "+f"(c[0]), "+f"(c[1]), "+f"(c[2]), "+f"(c[3])
        : "r"(a[0]), "r"(a[1]), "r"(a[2]), "r"(a[3]),
          "r"(b[0]), "r"(b[1]));
}

__device__ __forceinline__ void ldsm4(unsigned* d, uint32_t addr)
{
    asm volatile(
        "ldmatrix.sync.aligned.m8n8.x4.shared.b16 {%0,%1,%2,%3}, [%4];"
        : "=r"(d[0]), "=r"(d[1]), "=r"(d[2]), "=r"(d[3]) : "r"(addr));
}

__global__ __launch_bounds__(256)
void gemm_tanh_ef32(const float* __restrict__ A, int lda,
                    const float* __restrict__ Rr, int ldr,
                    const float* __restrict__ W,        // [Nout, K]
                    const float* __restrict__ bias,     // [Nout]
                    float* __restrict__ C, int ldc,
                    int K)
{
    // row layout (words): 0..7 = hi pairs (k0..15), 8..15 = lo pairs, 16..19 pad
    __shared__ unsigned As[2][BM][SROW];
    __shared__ unsigned Ws[2][BN][SROW];

    const int tid  = threadIdx.x;
    const int lane = tid & 31;
    const int warp = tid >> 5;
    const int wm   = warp >> 1;     // 0..3  (32 rows each)
    const int wn   = warp & 1;      // 0..1  (64 cols each)
    const int l4   = lane & 3;
    const int lg   = lane >> 2;
    const int row0 = blockIdx.y * BM;
    const int col0 = blockIdx.x * BN;

    float acc[2][8][4];
    #pragma unroll
    for (int i = 0; i < 2; i++)
        #pragma unroll
        for (int j = 0; j < 8; j++)
            #pragma unroll
            for (int k = 0; k < 4; k++) acc[i][j][k] = 0.f;

    // LDSM per-lane address offsets (in bytes), relative to tile base:
    //   A x4: m0 rows mb+0..7 @w0, m1 rows mb+8..15 @w0, m2 @w4, m3 @w4
    //   lane -> row = (lane & 15), word = (lane >> 4) * 4
    const uint32_t a_off = (uint32_t)(lane & 15) * (SROW * 4)
                         + (uint32_t)(lane >> 4) * 16;
    //   B x4 (two nt blocks): m0 rows nb+0..7 @w0 (k0-7), m1 same rows @w4
    //   (k8-15), m2 rows nb+8..15 @w0, m3 @w4.
    //   lane -> row = (lane&7) + ((lane>>4)<<3), word = ((lane>>3)&1)*4
    const uint32_t b_off = (uint32_t)((lane & 7) + ((lane >> 4) << 3)) * (SROW * 4)
                         + (uint32_t)((lane >> 3) & 1) * 16;

    // Loader: tile is 128 rows x 16 k-floats = 512 float4; 2 per thread.
    const int akq  = (tid & 3) * 4;   // k offset within tile (0,4,8,12)
    const int kp   = akq >> 1;        // word index base (0,2,4,6)
    const int arow = tid >> 2;        // row 0..63 (+64 on pass 2)

    float4 pa[2], pw[2];
    const int nk = K / BK;

    // prefetch tile 0
    #pragma unroll
    for (int i = 0; i < 2; i++) {
        int r = arow + i * 64;
        pa[i] = *(const float4*)(A + (size_t)(row0 + r) * lda + akq);
        if (Rr) {
            float4 t = *(const float4*)(Rr + (size_t)(row0 + r) * ldr + akq);
            pa[i].x += t.x; pa[i].y += t.y; pa[i].z += t.z; pa[i].w += t.w;
        }
        pw[i] = *(const float4*)(W + (size_t)(col0 + r) * K + akq);
    }

    for (int it = 0; it < nk; it++) {
        const int b = it & 1;

        // split fp32 -> bf16 hi/lo, store packed pairs
        #pragma unroll
        for (int i = 0; i < 2; i++) {
            int r = arow + i * 64;
            unsigned h0, l0, h1, l1;
            split2(pa[i].x, pa[i].y, h0, l0);
            split2(pa[i].z, pa[i].w, h1, l1);
            As[b][r][kp    ] = h0;  As[b][r][kp + 1] = h1;
            As[b][r][kp + 8] = l0;  As[b][r][kp + 9] = l1;
            split2(pw[i].x, pw[i].y, h0, l0);
            split2(pw[i].z, pw[i].w, h1, l1);
            Ws[b][r][kp    ] = h0;  Ws[b][r][kp + 1] = h1;
            Ws[b][r][kp + 8] = l0;  Ws[b][r][kp + 9] = l1;
        }
        __syncthreads();

        // prefetch next tile (overlaps MMA below)
        if (it + 1 < nk) {
            int kt = (it + 1) * BK;
            #pragma unroll
            for (int i = 0; i < 2; i++) {
                int r = arow + i * 64;
                pa[i] = *(const float4*)(A + (size_t)(row0 + r) * lda + kt + akq);
                if (Rr) {
                    float4 t = *(const float4*)(Rr + (size_t)(row0 + r) * ldr + kt + akq);
                    pa[i].x += t.x; pa[i].y += t.y; pa[i].z += t.z; pa[i].w += t.w;
                }
                pw[i] = *(const float4*)(W + (size_t)(col0 + r) * K + kt + akq);
            }
        }

        // ---- fragment loads via ldmatrix ----
        const uint32_t As_base = smem_u32(&As[b][0][0]);
        const uint32_t Ws_base = smem_u32(&Ws[b][0][0]);

        unsigned ah[2][4], al[2][4];
        #pragma unroll
        for (int mt = 0; mt < 2; mt++) {
            uint32_t base = As_base + (uint32_t)(wm * 32 + mt * 16) * (SROW * 4);
            ldsm4(ah[mt], base + a_off);        // hi: words 0..7
            ldsm4(al[mt], base + a_off + 32);   // lo: words 8..15
        }

        #pragma unroll
        for (int p = 0; p < 4; p++) {           // nt pair (2p, 2p+1)
            uint32_t base = Ws_base + (uint32_t)(wn * 64 + p * 16) * (SROW * 4);
            unsigned bh[4], bl[4];
            ldsm4(bh, base + b_off);            // hi
            ldsm4(bl, base + b_off + 32);       // lo
            #pragma unroll
            for (int h = 0; h < 2; h++) {       // nt = 2p + h
                int nt = 2 * p + h;
                #pragma unroll
                for (int mt = 0; mt < 2; mt++) {
                    mma_bf16(acc[mt][nt], ah[mt], bh + 2 * h);   // hi*hi
                    mma_bf16(acc[mt][nt], al[mt], bh + 2 * h);   // lo*hi
                    mma_bf16(acc[mt][nt], ah[mt], bl + 2 * h);   // hi*lo
                }
            }
        }
        // single barrier per iteration is sufficient: a warp storing buffer b
        // at iteration it+2 has passed the barrier at it+1, which every warp
        // reaches only after finishing compute of iteration it.
    }

    // epilogue: bias + tanh, float2 stores
    #pragma unroll
    for (int mt = 0; mt < 2; mt++) {
        int r = row0 + wm * 32 + mt * 16 + lg;
        #pragma unroll
        for (int nt = 0; nt < 8; nt++) {
            int c  = col0 + wn * 64 + nt * 8 + 2 * l4;
            float b0 = bias[c], b1 = bias[c + 1];
            float2 v;
            v.x = tanhf(acc[mt][nt][0] + b0);
            v.y = tanhf(acc[mt][nt][1] + b1);
            *(float2*)(C + (size_t)r * ldc + c) = v;
            v.x = tanhf(acc[mt][nt][2] + b0);
            v.y = tanhf(acc[mt][nt][3] + b1);
            *(float2*)(C + (size_t)(r + 8) * ldc + c) = v;
        }
    }
}

// msgs[n,:] = sum_{k<8} prev[idx[n,k], :]   (256 floats/row)
__global__ __launch_bounds__(256)
void gather_sum(const float* __restrict__ prev, const int* __restrict__ idx,
                float* __restrict__ outp)
{
    int n  = blockIdx.x * 4 + (threadIdx.x >> 6);
    int c4 = (threadIdx.x & 63) * 4;
    const int* ip = idx + (size_t)n * 8;
    float4 s = make_float4(0.f, 0.f, 0.f, 0.f);
    #pragma unroll
    for (int k = 0; k < 8; k++) {
        int j = __ldg(ip + k);
        float4 v = *(const float4*)(prev + (size_t)j * 256 + c4);
        s.x += v.x; s.y += v.y; s.z += v.z; s.w += v.w;
    }
    *(float4*)(outp + (size_t)n * 256 + c4) = s;
}

// zero upper half of X1 (the "concat with zeros" branch)
__global__ void zero_upper_k(float* X1)
{
    X1[(size_t)blockIdx.x * 512 + 256 + threadIdx.x] = 0.f;
}

// ---------------------------------------------------------------------------

extern "C" void kernel_launch(void* const* d_in, const int* in_sizes, int n_in,
                              void* d_out, int out_size)
{
    const float* feats = (const float*)d_in[0];   // [6, NN, 32]
    const int*   pred  = (const int*)  d_in[1];   // [5, NN, 8]
    const float* We    = (const float*)d_in[2];   // [256, 32]
    const float* be    = (const float*)d_in[3];   // [256]
    const float* rsW1  = (const float*)d_in[4];   // [12,256,256]
    const float* rsb1  = (const float*)d_in[5];
    const float* rsW2  = (const float*)d_in[6];
    const float* rsb2  = (const float*)d_in[7];
    const float* rsW3  = (const float*)d_in[8];
    const float* rsb3  = (const float*)d_in[9];
    const float* rcW1  = (const float*)d_in[10];  // [6,512,512]
    const float* rcb1  = (const float*)d_in[11];
    const float* rcW2  = (const float*)d_in[12];
    const float* rcb2  = (const float*)d_in[13];
    const float* rcW3  = (const float*)d_in[14];  // [6,256,512]
    const float* rcb3  = (const float*)d_in[15];
    float* out = (float*)d_out;                   // [6, NN, 256]

    float *X1, *X2, *H1, *H2, *T0, *T1, *T2, *MS;
    cudaGetSymbolAddress((void**)&X1, g_X1);
    cudaGetSymbolAddress((void**)&X2, g_X2);
    cudaGetSymbolAddress((void**)&H1, g_H1);
    cudaGetSymbolAddress((void**)&H2, g_H2);
    cudaGetSymbolAddress((void**)&T0, g_T0);
    cudaGetSymbolAddress((void**)&T1, g_T1);
    cudaGetSymbolAddress((void**)&T2, g_T2);
    cudaGetSymbolAddress((void**)&MS, g_MS);

    auto G = [&](const float* A, int lda, const float* R, int ldr,
                 const float* W, const float* b, float* C, int ldc,
                 int Nout, int K) {
        dim3 grid(Nout / BN, NN / BM);
        gemm_tanh_ef32<<<grid, 256>>>(A, lda, R, ldr, W, b, C, ldc, K);
    };

    // X1 upper 256 cols = zeros (concat(e, zeros)); stays zero all levels
    zero_upper_k<<<NN, 256>>>(X1);

    // level 0: out[0] = tanh(feats[0] @ We^T + be)
    G(feats, 32, nullptr, 0, We, be, out, 256, 256, 32);

    for (int l = 1; l < 6; l++) {
        int d = l - 1; if (d > 2) d = 2;
        const float* fl   = feats + (size_t)l * NN * 32;
        float*       OUT  = out   + (size_t)l * NN * 256;
        const float* PREV = out   + (size_t)(l - 1) * NN * 256;

        // embed -> X1[:, 0:256]
        G(fl, 32, nullptr, 0, We, be, X1, 512, 256, 32);

        // big resnet (3+d) on X1=[e,0]
        int bc = 3 + d;
        G(X1, 512, nullptr, 0, rcW1 + (size_t)bc * 512 * 512, rcb1 + bc * 512, H1, 512, 512, 512);
        G(H1, 512, nullptr, 0, rcW2 + (size_t)bc * 512 * 512, rcb2 + bc * 512, H2, 512, 512, 512);
        G(H2, 512, X1, 512,   rcW3 + (size_t)bc * 256 * 512, rcb3 + bc * 256, T0, 256, 256, 512);

        // small resnet (9+d) on z=T0 -> e1 into X2[:, 0:256]
        int s = 9 + d;
        G(T0, 256, nullptr, 0, rsW1 + (size_t)s * 65536, rsb1 + s * 256, T1, 256, 256, 256);
        G(T1, 256, nullptr, 0, rsW2 + (size_t)s * 65536, rsb2 + s * 256, T2, 256, 256, 256);
        G(T2, 256, T0, 256,    rsW3 + (size_t)s * 65536, rsb3 + s * 256, X2, 512, 256, 256);

        // messages: gather-sum predecessors from previous level
        gather_sum<<<NN / 4, 256>>>(PREV, pred + (size_t)(l - 1) * NN * 8, MS);

        // small resnet (2d) on msgs
        s = 2 * d;
        G(MS, 256, nullptr, 0, rsW1 + (size_t)s * 65536, rsb1 + s * 256, T0, 256, 256, 256);
        G(T0, 256, nullptr, 0, rsW2 + (size_t)s * 65536, rsb2 + s * 256, T1, 256, 256, 256);
        G(T1, 256, MS, 256,    rsW3 + (size_t)s * 65536, rsb3 + s * 256, T2, 256, 256, 256);

        // small resnet (2d+1) on r=T2 -> r into X2[:, 256:512]
        s = 2 * d + 1;
        G(T2, 256, nullptr, 0, rsW1 + (size_t)s * 65536, rsb1 + s * 256, T0, 256, 256, 256);
        G(T0, 256, nullptr, 0, rsW2 + (size_t)s * 65536, rsb2 + s * 256, T1, 256, 256, 256);
        G(T1, 256, T2, 256,    rsW3 + (size_t)s * 65536, rsb3 + s * 256, X2 + 256, 512, 256, 256);

        // big resnet (d) on X2=[e1, r]
        G(X2, 512, nullptr, 0, rcW1 + (size_t)d * 512 * 512, rcb1 + d * 512, H1, 512, 512, 512);
        G(H1, 512, nullptr, 0, rcW2 + (size_t)d * 512 * 512, rcb2 + d * 512, H2, 512, 512, 512);
        G(H2, 512, X2, 512,   rcW3 + (size_t)d * 256 * 512, rcb3 + d * 256, T0, 256, 256, 512);

        // small resnet (6+d) -> out[l]
        s = 6 + d;
        G(T0, 256, nullptr, 0, rsW1 + (size_t)s * 65536, rsb1 + s * 256, T1, 256, 256, 256);
        G(T1, 256, nullptr, 0, rsW2 + (size_t)s * 65536, rsb2 + s * 256, T2, 256, 256, 256);
        G(T2, 256, T0, 256,    rsW3 + (size_t)s * 65536, rsb3 + s * 256, OUT, 256, 256, 256);
    }
}